// round 11
// baseline (speedup 1.0000x reference)
#include <cuda_runtime.h>
#include <math_constants.h>
#include <cstdint>

#define BB 32
#define SS 480
#define DD 512
#define HH 8
#define DK 64
#define ML 500
#define QT 32
#define JT 128
#define QTP 36
#define JTP 132
#define PVQ 64
#define PVP 68

__device__ float g_q[BB*HH*SS*DK];
__device__ float g_k[BB*HH*SS*DK];
__device__ float g_v[BB*HH*SS*DK];
__device__ float g_ctx[(size_t)BB*SS*DD];
__device__ float g_p[(size_t)BB*HH*SS*SS];   // probs

// fast exp on the FMA pipe (no MUFU). x <= 0 here; -inf -> ~0.
__device__ __forceinline__ float fexp(float x) {
    float t = x * 1.4426950408889634f;          // log2(e)
    t = fmaxf(t, -126.0f);
    float fi = floorf(t);
    float f  = t - fi;
    // 2^f, f in [0,1): degree-6 Taylor of exp(f*ln2), Horner
    float p = 1.5252733804059840e-4f;
    p = fmaf(p, f, 1.3333558146428443e-3f);
    p = fmaf(p, f, 9.6181291076284771e-3f);
    p = fmaf(p, f, 5.5504108664798463e-2f);
    p = fmaf(p, f, 2.4022650695910071e-1f);
    p = fmaf(p, f, 6.9314718055994531e-1f);
    p = fmaf(p, f, 1.0f);
    int ei = (int)fi;
    float scale = __int_as_float((ei + 127) << 23);
    return p * scale;
}

// ---------------------------------------------------------------------------
// Kernel 1: fused QKV projection (unchanged from R10).
// ---------------------------------------------------------------------------
__global__ __launch_bounds__(128) void proj_qkv(
    const float* __restrict__ x,
    const float* __restrict__ wq, const float* __restrict__ bq,
    const float* __restrict__ wk, const float* __restrict__ bk,
    const float* __restrict__ wv, const float* __restrict__ bv)
{
    const int z = blockIdx.z;
    const float* W    = (z == 0) ? wq : (z == 1) ? wk : wv;
    const float* bias = (z == 0) ? bq : (z == 1) ? bk : bv;
    float* Out        = (z == 0) ? g_q : (z == 1) ? g_k : g_v;

    __shared__ float Xs[32][132];
    __shared__ float Ws[32][68];

    const int m0 = blockIdx.x * 64;
    const int n0 = blockIdx.y * 128;
    const int tid = threadIdx.x;

    const int c8 = tid & 7,  xrow = tid >> 3;
    const int wc4 = tid & 15, wk_ = tid >> 4;
    const int ri = tid >> 3, ci = tid & 7;

    float acc[8][8] = {};
    float4 xr[8], wr[4];

#pragma unroll
    for (int rr = 0; rr < 8; rr++)
        xr[rr] = *(const float4*)&x[(size_t)(n0 + xrow + rr*16)*DD + c8*4];
#pragma unroll
    for (int tt = 0; tt < 4; tt++)
        wr[tt] = *(const float4*)&W[(size_t)(wk_ + tt*8)*DD + m0 + wc4*4];

    for (int k0 = 0; k0 < DD; k0 += 32) {
#pragma unroll
        for (int rr = 0; rr < 8; rr++) {
            int r = xrow + rr*16;
            Xs[c8*4+0][r] = xr[rr].x; Xs[c8*4+1][r] = xr[rr].y;
            Xs[c8*4+2][r] = xr[rr].z; Xs[c8*4+3][r] = xr[rr].w;
        }
#pragma unroll
        for (int tt = 0; tt < 4; tt++)
            *(float4*)&Ws[wk_ + tt*8][wc4*4] = wr[tt];
        __syncthreads();

        if (k0 + 32 < DD) {
#pragma unroll
            for (int rr = 0; rr < 8; rr++)
                xr[rr] = *(const float4*)&x[(size_t)(n0 + xrow + rr*16)*DD + k0 + 32 + c8*4];
#pragma unroll
            for (int tt = 0; tt < 4; tt++)
                wr[tt] = *(const float4*)&W[(size_t)(k0 + 32 + wk_ + tt*8)*DD + m0 + wc4*4];
        }

#pragma unroll
        for (int t = 0; t < 32; t++) {
            float4 a0 = *(const float4*)&Xs[t][ri*8];
            float4 a1 = *(const float4*)&Xs[t][ri*8+4];
            float4 b0 = *(const float4*)&Ws[t][ci*8];
            float4 b1 = *(const float4*)&Ws[t][ci*8+4];
            float av[8] = {a0.x,a0.y,a0.z,a0.w,a1.x,a1.y,a1.z,a1.w};
            float bw[8] = {b0.x,b0.y,b0.z,b0.w,b1.x,b1.y,b1.z,b1.w};
#pragma unroll
            for (int i = 0; i < 8; i++)
#pragma unroll
                for (int j = 0; j < 8; j++)
                    acc[i][j] += av[i] * bw[j];
        }
        __syncthreads();
    }

    const int h = m0 >> 6;
    const int d = ci*8;
    float4 bb0 = *(const float4*)&bias[m0 + d];
    float4 bb1 = *(const float4*)&bias[m0 + d + 4];
#pragma unroll
    for (int u = 0; u < 8; u++) {
        int n = n0 + ri*8 + u;
        int b = n / SS, s = n % SS;
        float* dst = &Out[(((size_t)b*HH + h)*SS + s)*DK + d];
        *(float4*)&dst[0] = make_float4(acc[u][0]+bb0.x, acc[u][1]+bb0.y,
                                        acc[u][2]+bb0.z, acc[u][3]+bb0.w);
        *(float4*)&dst[4] = make_float4(acc[u][4]+bb1.x, acc[u][5]+bb1.y,
                                        acc[u][6]+bb1.z, acc[u][7]+bb1.w);
    }
}

// ---------------------------------------------------------------------------
// Kernel 2: scores + softmax (polynomial exp) + write probs P.
// ---------------------------------------------------------------------------
__global__ __launch_bounds__(256, 2) void scores_kernel(
    const float* __restrict__ rel_bias)
{
    extern __shared__ float smem[];
    float* sc  = smem;
    float* qsT = sc + QT*SS;
    float* kvb = qsT + 64*QTP;

    const int i0 = blockIdx.x * QT;
    const int h  = blockIdx.y;
    const int b  = blockIdx.z;
    const int tid = threadIdx.x;
    const int lane = tid & 31, warp = tid >> 5;

    const int jcount = i0 + QT;
    const int ntile  = (jcount + JT - 1) / JT;
    const int jcap   = min(SS, ntile * JT);

    const float* qg = g_q + (((size_t)b*HH + h)*SS + i0)*DK;
    const float* kg = g_k + (((size_t)b*HH + h)*SS)*DK;

    for (int idx = tid; idx < QT*DK; idx += 256) {
        int i = idx >> 6, t = idx & 63;
        qsT[t*QTP + i] = qg[idx];
    }

    for (int jt = 0; jt < ntile; jt++) {
        int j0 = jt * JT;
        __syncthreads();
        for (int idx = tid; idx < JT*DK; idx += 256) {
            int jl = idx >> 6, t = idx & 63;
            int j = j0 + jl;
            kvb[t*JTP + jl] = (j < SS) ? kg[(size_t)j*DK + t] : 0.f;
        }
        __syncthreads();
        const int ti = (tid >> 5) * 4;
        const int tj = (tid & 31) * 4;
        float acc[4][4] = {};
#pragma unroll
        for (int t = 0; t < 64; t++) {
            float4 a4 = *(const float4*)&qsT[t*QTP + ti];
            float4 b4 = *(const float4*)&kvb[t*JTP + tj];
            float av[4] = {a4.x, a4.y, a4.z, a4.w};
            float bw[4] = {b4.x, b4.y, b4.z, b4.w};
#pragma unroll
            for (int i = 0; i < 4; i++)
#pragma unroll
                for (int j = 0; j < 4; j++)
                    acc[i][j] += av[i] * bw[j];
        }
#pragma unroll
        for (int ii = 0; ii < 4; ii++) {
            int i = i0 + ti + ii;
            const float* brow = rel_bias + ((size_t)h*ML + i)*ML;
            float4 bias4;
            if (j0 + tj + 3 < SS) bias4 = *(const float4*)&brow[j0 + tj];
            else {
                bias4.x = (j0+tj   < SS) ? brow[j0+tj]   : 0.f;
                bias4.y = (j0+tj+1 < SS) ? brow[j0+tj+1] : 0.f;
                bias4.z = (j0+tj+2 < SS) ? brow[j0+tj+2] : 0.f;
                bias4.w = (j0+tj+3 < SS) ? brow[j0+tj+3] : 0.f;
            }
            float bb4[4] = {bias4.x, bias4.y, bias4.z, bias4.w};
            float vals[4];
#pragma unroll
            for (int jj = 0; jj < 4; jj++) {
                int j = j0 + tj + jj;
                vals[jj] = (j <= i && j < SS) ? acc[ii][jj]*0.125f + bb4[jj]
                                              : -CUDART_INF_F;
            }
            if (j0 + JT <= SS) {
                *(float4*)&sc[(ti+ii)*SS + j0 + tj] =
                    make_float4(vals[0], vals[1], vals[2], vals[3]);
            } else {
#pragma unroll
                for (int jj = 0; jj < 4; jj++) {
                    int j = j0 + tj + jj;
                    if (j < SS) sc[(ti+ii)*SS + j] = vals[jj];
                }
            }
        }
    }
    __syncthreads();

    for (int r = warp; r < QT; r += 8) {
        float* row = sc + r*SS;
        float m = -CUDART_INF_F;
        for (int j = lane; j < jcap; j += 32) m = fmaxf(m, row[j]);
#pragma unroll
        for (int o = 16; o; o >>= 1) m = fmaxf(m, __shfl_xor_sync(0xffffffffu, m, o));
        float ssum = 0.f;
        for (int j = lane; j < jcap; j += 32) {
            float e = fexp(row[j] - m);
            row[j] = e;
            ssum += e;
        }
#pragma unroll
        for (int o = 16; o; o >>= 1) ssum += __shfl_xor_sync(0xffffffffu, ssum, o);
        float inv = 1.f / ssum;
        for (int j = lane; j < jcap; j += 32) row[j] *= inv;
    }
    __syncthreads();

    float* pg = g_p + (((size_t)b*HH + h)*SS + i0)*SS;
    const int nq4 = jcap >> 2;
    for (int idx = tid; idx < QT*nq4; idx += 256) {
        int r = idx / nq4, c4 = idx - r*nq4;
        *(float4*)&pg[(size_t)r*SS + c4*4] = *(const float4*)&sc[r*SS + c4*4];
    }
}

// ---------------------------------------------------------------------------
// Kernel 3: attn mean over heads (unchanged).
// ---------------------------------------------------------------------------
__global__ __launch_bounds__(256) void mean_kernel(float* __restrict__ out_attn)
{
    const int gid = blockIdx.x * 256 + threadIdx.x;
    const int j4  = gid % (SS/4);
    int rest = gid / (SS/4);
    const int i = rest % SS;
    const int b = rest / SS;

    const int i0 = (i >> 5) << 5;
    const int jcap = min(SS, (((i0 + QT) + JT - 1) / JT) * JT);

    float4 s = make_float4(0.f, 0.f, 0.f, 0.f);
    if (j4*4 < jcap) {
        const float* base = g_p + (((size_t)b*HH)*SS + i)*SS + j4*4;
#pragma unroll
        for (int h = 0; h < HH; h++) {
            float4 v = *(const float4*)(base + (size_t)h*SS*SS);
            s.x += v.x; s.y += v.y; s.z += v.z; s.w += v.w;
        }
        s.x *= 0.125f; s.y *= 0.125f; s.z *= 0.125f; s.w *= 0.125f;
    }
    *(float4*)&out_attn[((size_t)b*SS + i)*SS + j4*4] = s;
}

// ---------------------------------------------------------------------------
// Kernel 4: ctx = P @ V.  (R10 layout; launch_bounds forces 3 CTAs/SM.)
// ---------------------------------------------------------------------------
__global__ __launch_bounds__(256, 3) void pv_kernel()
{
    extern __shared__ float pvsm[];
    float* psT = pvsm;
    float* vs  = psT + JT*PVP;

    const int i0 = blockIdx.x * PVQ;
    const int h  = blockIdx.y;
    const int b  = blockIdx.z;
    const int tid = threadIdx.x;

    const int jcount = min(i0 + PVQ, SS);
    const int ntile  = (jcount + JT - 1) / JT;

    const float* vg = g_v + (((size_t)b*HH + h)*SS)*DK;
    const float* pg = g_p + (((size_t)b*HH + h)*SS + i0)*SS;

    const int rg = tid >> 4;
    const int cg = tid & 15;

    float acc[4][4] = {};

    for (int jt = 0; jt < ntile; jt++) {
        const int j0 = jt * JT;
        __syncthreads();
#pragma unroll
        for (int it = 0; it < 8; it++) {
            int idx = tid + it*256;
            int j = idx >> 4, d4 = idx & 15;
            float4 v = (j0 + j < SS)
                ? *(const float4*)&vg[(size_t)(j0 + j)*DK + d4*4]
                : make_float4(0.f,0.f,0.f,0.f);
            *(float4*)&vs[j*64 + d4*4] = v;
        }
#pragma unroll
        for (int it = 0; it < 32; it++) {
            int idx = tid + it*256;
            int r = idx >> 7, j = idx & 127;
            float p = (i0 + r < SS && j0 + j < SS) ? pg[(size_t)r*SS + j0 + j] : 0.f;
            psT[j*PVP + r] = p;
        }
        __syncthreads();

#pragma unroll 8
        for (int j = 0; j < JT; j++) {
            float4 a4 = *(const float4*)&psT[j*PVP + rg*4];
            float4 b4 = *(const float4*)&vs[j*64 + cg*4];
            float av[4] = {a4.x, a4.y, a4.z, a4.w};
            float bw[4] = {b4.x, b4.y, b4.z, b4.w};
#pragma unroll
            for (int i = 0; i < 4; i++)
#pragma unroll
                for (int c = 0; c < 4; c++)
                    acc[i][c] += av[i] * bw[c];
        }
    }

#pragma unroll
    for (int i = 0; i < 4; i++) {
        int row = i0 + rg*4 + i;
        if (row < SS) {
            float* dst = g_ctx + ((size_t)b*SS + row)*DD + h*DK + cg*4;
            *(float4*)dst = make_float4(acc[i][0], acc[i][1], acc[i][2], acc[i][3]);
        }
    }
}

// ---------------------------------------------------------------------------
// Kernel 5: output projection (unchanged from R10).
// ---------------------------------------------------------------------------
__global__ __launch_bounds__(128) void out_proj(
    const float* __restrict__ wo, const float* __restrict__ bo,
    float* __restrict__ out)
{
    __shared__ float Xs[32][132];
    __shared__ float Ws[32][68];

    const int m0 = blockIdx.x * 64;
    const int n0 = blockIdx.y * 128;
    const int tid = threadIdx.x;

    const int c8 = tid & 7,  xrow = tid >> 3;
    const int wc4 = tid & 15, wk_ = tid >> 4;
    const int ri = tid >> 3, ci = tid & 7;

    float acc[8][8] = {};
    float4 xr[8], wr[4];

#pragma unroll
    for (int rr = 0; rr < 8; rr++)
        xr[rr] = *(const float4*)&g_ctx[(size_t)(n0 + xrow + rr*16)*DD + c8*4];
#pragma unroll
    for (int tt = 0; tt < 4; tt++)
        wr[tt] = *(const float4*)&wo[(size_t)(wk_ + tt*8)*DD + m0 + wc4*4];

    for (int k0 = 0; k0 < DD; k0 += 32) {
#pragma unroll
        for (int rr = 0; rr < 8; rr++) {
            int r = xrow + rr*16;
            Xs[c8*4+0][r] = xr[rr].x; Xs[c8*4+1][r] = xr[rr].y;
            Xs[c8*4+2][r] = xr[rr].z; Xs[c8*4+3][r] = xr[rr].w;
        }
#pragma unroll
        for (int tt = 0; tt < 4; tt++)
            *(float4*)&Ws[wk_ + tt*8][wc4*4] = wr[tt];
        __syncthreads();

        if (k0 + 32 < DD) {
#pragma unroll
            for (int rr = 0; rr < 8; rr++)
                xr[rr] = *(const float4*)&g_ctx[(size_t)(n0 + xrow + rr*16)*DD + k0 + 32 + c8*4];
#pragma unroll
            for (int tt = 0; tt < 4; tt++)
                wr[tt] = *(const float4*)&wo[(size_t)(k0 + 32 + wk_ + tt*8)*DD + m0 + wc4*4];
        }

#pragma unroll
        for (int t = 0; t < 32; t++) {
            float4 a0 = *(const float4*)&Xs[t][ri*8];
            float4 a1 = *(const float4*)&Xs[t][ri*8+4];
            float4 b0 = *(const float4*)&Ws[t][ci*8];
            float4 b1 = *(const float4*)&Ws[t][ci*8+4];
            float av[8] = {a0.x,a0.y,a0.z,a0.w,a1.x,a1.y,a1.z,a1.w};
            float bw[8] = {b0.x,b0.y,b0.z,b0.w,b1.x,b1.y,b1.z,b1.w};
#pragma unroll
            for (int i = 0; i < 8; i++)
#pragma unroll
                for (int j = 0; j < 8; j++)
                    acc[i][j] += av[i] * bw[j];
        }
        __syncthreads();
    }

    const int d = ci*8;
    float4 bb0 = *(const float4*)&bo[m0 + d];
    float4 bb1 = *(const float4*)&bo[m0 + d + 4];
#pragma unroll
    for (int u = 0; u < 8; u++) {
        int n = n0 + ri*8 + u;
        float* dst = &out[(size_t)n*DD + m0 + d];
        *(float4*)&dst[0] = make_float4(acc[u][0]+bb0.x, acc[u][1]+bb0.y,
                                        acc[u][2]+bb0.z, acc[u][3]+bb0.w);
        *(float4*)&dst[4] = make_float4(acc[u][4]+bb1.x, acc[u][5]+bb1.y,
                                        acc[u][6]+bb1.z, acc[u][7]+bb1.w);
    }
}

// ---------------------------------------------------------------------------

static const int SC_SMEM = (QT*SS + 64*QTP + 64*JTP) * (int)sizeof(float); // 104448
static const int PV_SMEM = (JT*PVP + JT*64) * (int)sizeof(float);          // 67584

extern "C" void kernel_launch(void* const* d_in, const int* in_sizes, int n_in,
                              void* d_out, int out_size) {
    const float* x  = (const float*)d_in[0];
    const float* wq = (const float*)d_in[1];
    const float* bq = (const float*)d_in[2];
    const float* wk = (const float*)d_in[3];
    const float* bk = (const float*)d_in[4];
    const float* wv = (const float*)d_in[5];
    const float* bv = (const float*)d_in[6];
    const float* wo = (const float*)d_in[7];
    const float* bo = (const float*)d_in[8];
    const float* rb = (const float*)d_in[9];

    float* out      = (float*)d_out;
    float* out_attn = out + (size_t)BB*SS*DD;

    cudaFuncSetAttribute(scores_kernel, cudaFuncAttributeMaxDynamicSharedMemorySize, SC_SMEM);
    cudaFuncSetAttribute(pv_kernel, cudaFuncAttributeMaxDynamicSharedMemorySize, PV_SMEM);

    proj_qkv<<<dim3(DD/64, (BB*SS)/128, 3), 128>>>(x, wq, bq, wk, bk, wv, bv);

    scores_kernel<<<dim3(SS/QT, HH, BB), 256, SC_SMEM>>>(rb);

    mean_kernel<<<(BB*SS*(SS/4))/256, 256>>>(out_attn);

    pv_kernel<<<dim3((SS + PVQ - 1)/PVQ, HH, BB), 256, PV_SMEM>>>();

    out_proj<<<dim3(DD/64, (BB*SS)/128), 128>>>(wo, bo, out);
}

// round 12
// speedup vs baseline: 1.0048x; 1.0048x over previous
#include <cuda_runtime.h>
#include <math_constants.h>
#include <cstdint>

#define BB 32
#define SS 480
#define DD 512
#define HH 8
#define DK 64
#define ML 500
#define QT 32
#define JT 128
#define QTP 36
#define JTP 132
#define PVQ 128
#define PVP 132

__device__ float g_q[BB*HH*SS*DK];
__device__ float g_k[BB*HH*SS*DK];
__device__ float g_v[BB*HH*SS*DK];
__device__ float g_ctx[(size_t)BB*SS*DD];
__device__ float g_p[(size_t)BB*HH*SS*SS];   // probs

// ---------------------------------------------------------------------------
// Kernel 1: fused QKV projection (R10 version — known good).
// ---------------------------------------------------------------------------
__global__ __launch_bounds__(128) void proj_qkv(
    const float* __restrict__ x,
    const float* __restrict__ wq, const float* __restrict__ bq,
    const float* __restrict__ wk, const float* __restrict__ bk,
    const float* __restrict__ wv, const float* __restrict__ bv)
{
    const int z = blockIdx.z;
    const float* W    = (z == 0) ? wq : (z == 1) ? wk : wv;
    const float* bias = (z == 0) ? bq : (z == 1) ? bk : bv;
    float* Out        = (z == 0) ? g_q : (z == 1) ? g_k : g_v;

    __shared__ float Xs[32][132];
    __shared__ float Ws[32][68];

    const int m0 = blockIdx.x * 64;
    const int n0 = blockIdx.y * 128;
    const int tid = threadIdx.x;

    const int c8 = tid & 7,  xrow = tid >> 3;
    const int wc4 = tid & 15, wk_ = tid >> 4;
    const int ri = tid >> 3, ci = tid & 7;

    float acc[8][8] = {};
    float4 xr[8], wr[4];

#pragma unroll
    for (int rr = 0; rr < 8; rr++)
        xr[rr] = *(const float4*)&x[(size_t)(n0 + xrow + rr*16)*DD + c8*4];
#pragma unroll
    for (int tt = 0; tt < 4; tt++)
        wr[tt] = *(const float4*)&W[(size_t)(wk_ + tt*8)*DD + m0 + wc4*4];

    for (int k0 = 0; k0 < DD; k0 += 32) {
#pragma unroll
        for (int rr = 0; rr < 8; rr++) {
            int r = xrow + rr*16;
            Xs[c8*4+0][r] = xr[rr].x; Xs[c8*4+1][r] = xr[rr].y;
            Xs[c8*4+2][r] = xr[rr].z; Xs[c8*4+3][r] = xr[rr].w;
        }
#pragma unroll
        for (int tt = 0; tt < 4; tt++)
            *(float4*)&Ws[wk_ + tt*8][wc4*4] = wr[tt];
        __syncthreads();

        if (k0 + 32 < DD) {
#pragma unroll
            for (int rr = 0; rr < 8; rr++)
                xr[rr] = *(const float4*)&x[(size_t)(n0 + xrow + rr*16)*DD + k0 + 32 + c8*4];
#pragma unroll
            for (int tt = 0; tt < 4; tt++)
                wr[tt] = *(const float4*)&W[(size_t)(k0 + 32 + wk_ + tt*8)*DD + m0 + wc4*4];
        }

#pragma unroll
        for (int t = 0; t < 32; t++) {
            float4 a0 = *(const float4*)&Xs[t][ri*8];
            float4 a1 = *(const float4*)&Xs[t][ri*8+4];
            float4 b0 = *(const float4*)&Ws[t][ci*8];
            float4 b1 = *(const float4*)&Ws[t][ci*8+4];
            float av[8] = {a0.x,a0.y,a0.z,a0.w,a1.x,a1.y,a1.z,a1.w};
            float bw[8] = {b0.x,b0.y,b0.z,b0.w,b1.x,b1.y,b1.z,b1.w};
#pragma unroll
            for (int i = 0; i < 8; i++)
#pragma unroll
                for (int j = 0; j < 8; j++)
                    acc[i][j] += av[i] * bw[j];
        }
        __syncthreads();
    }

    const int h = m0 >> 6;
    const int d = ci*8;
    float4 bb0 = *(const float4*)&bias[m0 + d];
    float4 bb1 = *(const float4*)&bias[m0 + d + 4];
#pragma unroll
    for (int u = 0; u < 8; u++) {
        int n = n0 + ri*8 + u;
        int b = n / SS, s = n % SS;
        float* dst = &Out[(((size_t)b*HH + h)*SS + s)*DK + d];
        *(float4*)&dst[0] = make_float4(acc[u][0]+bb0.x, acc[u][1]+bb0.y,
                                        acc[u][2]+bb0.z, acc[u][3]+bb0.w);
        *(float4*)&dst[4] = make_float4(acc[u][4]+bb1.x, acc[u][5]+bb1.y,
                                        acc[u][6]+bb1.z, acc[u][7]+bb1.w);
    }
}

// ---------------------------------------------------------------------------
// Kernel 2: scores + softmax (__expf) + write probs P.  (R10 version)
// ---------------------------------------------------------------------------
__global__ __launch_bounds__(256, 2) void scores_kernel(
    const float* __restrict__ rel_bias)
{
    extern __shared__ float smem[];
    float* sc  = smem;
    float* qsT = sc + QT*SS;
    float* kvb = qsT + 64*QTP;

    const int i0 = blockIdx.x * QT;
    const int h  = blockIdx.y;
    const int b  = blockIdx.z;
    const int tid = threadIdx.x;
    const int lane = tid & 31, warp = tid >> 5;

    const int jcount = i0 + QT;
    const int ntile  = (jcount + JT - 1) / JT;
    const int jcap   = min(SS, ntile * JT);

    const float* qg = g_q + (((size_t)b*HH + h)*SS + i0)*DK;
    const float* kg = g_k + (((size_t)b*HH + h)*SS)*DK;

    for (int idx = tid; idx < QT*DK; idx += 256) {
        int i = idx >> 6, t = idx & 63;
        qsT[t*QTP + i] = qg[idx];
    }

    for (int jt = 0; jt < ntile; jt++) {
        int j0 = jt * JT;
        __syncthreads();
        for (int idx = tid; idx < JT*DK; idx += 256) {
            int jl = idx >> 6, t = idx & 63;
            int j = j0 + jl;
            kvb[t*JTP + jl] = (j < SS) ? kg[(size_t)j*DK + t] : 0.f;
        }
        __syncthreads();
        const int ti = (tid >> 5) * 4;
        const int tj = (tid & 31) * 4;
        float acc[4][4] = {};
#pragma unroll
        for (int t = 0; t < 64; t++) {
            float4 a4 = *(const float4*)&qsT[t*QTP + ti];
            float4 b4 = *(const float4*)&kvb[t*JTP + tj];
            float av[4] = {a4.x, a4.y, a4.z, a4.w};
            float bw[4] = {b4.x, b4.y, b4.z, b4.w};
#pragma unroll
            for (int i = 0; i < 4; i++)
#pragma unroll
                for (int j = 0; j < 4; j++)
                    acc[i][j] += av[i] * bw[j];
        }
#pragma unroll
        for (int ii = 0; ii < 4; ii++) {
            int i = i0 + ti + ii;
            const float* brow = rel_bias + ((size_t)h*ML + i)*ML;
            float4 bias4;
            if (j0 + tj + 3 < SS) bias4 = *(const float4*)&brow[j0 + tj];
            else {
                bias4.x = (j0+tj   < SS) ? brow[j0+tj]   : 0.f;
                bias4.y = (j0+tj+1 < SS) ? brow[j0+tj+1] : 0.f;
                bias4.z = (j0+tj+2 < SS) ? brow[j0+tj+2] : 0.f;
                bias4.w = (j0+tj+3 < SS) ? brow[j0+tj+3] : 0.f;
            }
            float bb4[4] = {bias4.x, bias4.y, bias4.z, bias4.w};
            float vals[4];
#pragma unroll
            for (int jj = 0; jj < 4; jj++) {
                int j = j0 + tj + jj;
                vals[jj] = (j <= i && j < SS) ? acc[ii][jj]*0.125f + bb4[jj]
                                              : -CUDART_INF_F;
            }
            if (j0 + JT <= SS) {
                *(float4*)&sc[(ti+ii)*SS + j0 + tj] =
                    make_float4(vals[0], vals[1], vals[2], vals[3]);
            } else {
#pragma unroll
                for (int jj = 0; jj < 4; jj++) {
                    int j = j0 + tj + jj;
                    if (j < SS) sc[(ti+ii)*SS + j] = vals[jj];
                }
            }
        }
    }
    __syncthreads();

    for (int r = warp; r < QT; r += 8) {
        float* row = sc + r*SS;
        float m = -CUDART_INF_F;
        for (int j = lane; j < jcap; j += 32) m = fmaxf(m, row[j]);
#pragma unroll
        for (int o = 16; o; o >>= 1) m = fmaxf(m, __shfl_xor_sync(0xffffffffu, m, o));
        float ssum = 0.f;
        for (int j = lane; j < jcap; j += 32) {
            float e = __expf(row[j] - m);
            row[j] = e;
            ssum += e;
        }
#pragma unroll
        for (int o = 16; o; o >>= 1) ssum += __shfl_xor_sync(0xffffffffu, ssum, o);
        float inv = 1.f / ssum;
        for (int j = lane; j < jcap; j += 32) row[j] *= inv;
    }
    __syncthreads();

    float* pg = g_p + (((size_t)b*HH + h)*SS + i0)*SS;
    const int nq4 = jcap >> 2;
    for (int idx = tid; idx < QT*nq4; idx += 256) {
        int r = idx / nq4, c4 = idx - r*nq4;
        *(float4*)&pg[(size_t)r*SS + c4*4] = *(const float4*)&sc[r*SS + c4*4];
    }
}

// ---------------------------------------------------------------------------
// Kernel 3: attn mean over heads (unchanged).
// ---------------------------------------------------------------------------
__global__ __launch_bounds__(256) void mean_kernel(float* __restrict__ out_attn)
{
    const int gid = blockIdx.x * 256 + threadIdx.x;
    const int j4  = gid % (SS/4);
    int rest = gid / (SS/4);
    const int i = rest % SS;
    const int b = rest / SS;

    const int i0 = (i >> 5) << 5;
    const int jcap = min(SS, (((i0 + QT) + JT - 1) / JT) * JT);

    float4 s = make_float4(0.f, 0.f, 0.f, 0.f);
    if (j4*4 < jcap) {
        const float* base = g_p + (((size_t)b*HH)*SS + i)*SS + j4*4;
#pragma unroll
        for (int h = 0; h < HH; h++) {
            float4 v = *(const float4*)(base + (size_t)h*SS*SS);
            s.x += v.x; s.y += v.y; s.z += v.z; s.w += v.w;
        }
        s.x *= 0.125f; s.y *= 0.125f; s.z *= 0.125f; s.w *= 0.125f;
    }
    *(float4*)&out_attn[((size_t)b*SS + i)*SS + j4*4] = s;
}

// ---------------------------------------------------------------------------
// Kernel 4: ctx = P @ V.  256 threads, C tile 128x64, thread tile 8x4.
// Per j-step: 3 LDS.128 -> 32 FMA (FMA-bound).  V traffic halved vs PVQ=64.
// ---------------------------------------------------------------------------
__global__ __launch_bounds__(256, 2) void pv_kernel()
{
    extern __shared__ float pvsm[];
    float* psT = pvsm;              // JT * PVP  (j-major, transposed P)
    float* vs  = psT + JT*PVP;      // JT * 64

    const int i0 = blockIdx.x * PVQ;
    const int h  = blockIdx.y;
    const int b  = blockIdx.z;
    const int tid = threadIdx.x;

    const int jcount = min(i0 + PVQ, SS);
    const int ntile  = (jcount + JT - 1) / JT;

    const float* vg = g_v + (((size_t)b*HH + h)*SS)*DK;
    const float* pg = g_p + (((size_t)b*HH + h)*SS + i0)*SS;

    const int rg = tid >> 4;      // 16 rowgroups of 8  (128 rows)
    const int cg = tid & 15;      // 16 colgroups of 4  (64 cols)

    float acc[8][4] = {};

    for (int jt = 0; jt < ntile; jt++) {
        const int j0 = jt * JT;
        __syncthreads();
        // V tile [j][d]: 2048 float4 / 256 thr = 8 iters
#pragma unroll
        for (int it = 0; it < 8; it++) {
            int idx = tid + it*256;
            int j = idx >> 4, d4 = idx & 15;
            float4 v = (j0 + j < SS)
                ? *(const float4*)&vg[(size_t)(j0 + j)*DK + d4*4]
                : make_float4(0.f,0.f,0.f,0.f);
            *(float4*)&vs[j*64 + d4*4] = v;
        }
        // P tile transposed: 128 rows x 128 j = 16384 scalars / 256 = 64 iters
#pragma unroll
        for (int it = 0; it < 64; it++) {
            int idx = tid + it*256;
            int r = idx >> 7, j = idx & 127;
            float p = (i0 + r < SS && j0 + j < SS) ? pg[(size_t)r*SS + j0 + j] : 0.f;
            psT[j*PVP + r] = p;
        }
        __syncthreads();

#pragma unroll 4
        for (int j = 0; j < JT; j++) {
            float4 a0 = *(const float4*)&psT[j*PVP + rg*8];
            float4 a1 = *(const float4*)&psT[j*PVP + rg*8 + 4];
            float4 b4 = *(const float4*)&vs[j*64 + cg*4];
            float av[8] = {a0.x,a0.y,a0.z,a0.w,a1.x,a1.y,a1.z,a1.w};
            float bw[4] = {b4.x,b4.y,b4.z,b4.w};
#pragma unroll
            for (int i = 0; i < 8; i++)
#pragma unroll
                for (int c = 0; c < 4; c++)
                    acc[i][c] += av[i] * bw[c];
        }
    }

#pragma unroll
    for (int i = 0; i < 8; i++) {
        int row = i0 + rg*8 + i;
        if (row < SS) {
            float* dst = g_ctx + ((size_t)b*SS + row)*DD + h*DK + cg*4;
            *(float4*)dst = make_float4(acc[i][0], acc[i][1], acc[i][2], acc[i][3]);
        }
    }
}

// ---------------------------------------------------------------------------
// Kernel 5: output projection (R10 version).
// ---------------------------------------------------------------------------
__global__ __launch_bounds__(128) void out_proj(
    const float* __restrict__ wo, const float* __restrict__ bo,
    float* __restrict__ out)
{
    __shared__ float Xs[32][132];
    __shared__ float Ws[32][68];

    const int m0 = blockIdx.x * 64;
    const int n0 = blockIdx.y * 128;
    const int tid = threadIdx.x;

    const int c8 = tid & 7,  xrow = tid >> 3;
    const int wc4 = tid & 15, wk_ = tid >> 4;
    const int ri = tid >> 3, ci = tid & 7;

    float acc[8][8] = {};
    float4 xr[8], wr[4];

#pragma unroll
    for (int rr = 0; rr < 8; rr++)
        xr[rr] = *(const float4*)&g_ctx[(size_t)(n0 + xrow + rr*16)*DD + c8*4];
#pragma unroll
    for (int tt = 0; tt < 4; tt++)
        wr[tt] = *(const float4*)&wo[(size_t)(wk_ + tt*8)*DD + m0 + wc4*4];

    for (int k0 = 0; k0 < DD; k0 += 32) {
#pragma unroll
        for (int rr = 0; rr < 8; rr++) {
            int r = xrow + rr*16;
            Xs[c8*4+0][r] = xr[rr].x; Xs[c8*4+1][r] = xr[rr].y;
            Xs[c8*4+2][r] = xr[rr].z; Xs[c8*4+3][r] = xr[rr].w;
        }
#pragma unroll
        for (int tt = 0; tt < 4; tt++)
            *(float4*)&Ws[wk_ + tt*8][wc4*4] = wr[tt];
        __syncthreads();

        if (k0 + 32 < DD) {
#pragma unroll
            for (int rr = 0; rr < 8; rr++)
                xr[rr] = *(const float4*)&g_ctx[(size_t)(n0 + xrow + rr*16)*DD + k0 + 32 + c8*4];
#pragma unroll
            for (int tt = 0; tt < 4; tt++)
                wr[tt] = *(const float4*)&wo[(size_t)(k0 + 32 + wk_ + tt*8)*DD + m0 + wc4*4];
        }

#pragma unroll
        for (int t = 0; t < 32; t++) {
            float4 a0 = *(const float4*)&Xs[t][ri*8];
            float4 a1 = *(const float4*)&Xs[t][ri*8+4];
            float4 b0 = *(const float4*)&Ws[t][ci*8];
            float4 b1 = *(const float4*)&Ws[t][ci*8+4];
            float av[8] = {a0.x,a0.y,a0.z,a0.w,a1.x,a1.y,a1.z,a1.w};
            float bw[8] = {b0.x,b0.y,b0.z,b0.w,b1.x,b1.y,b1.z,b1.w};
#pragma unroll
            for (int i = 0; i < 8; i++)
#pragma unroll
                for (int j = 0; j < 8; j++)
                    acc[i][j] += av[i] * bw[j];
        }
        __syncthreads();
    }

    const int d = ci*8;
    float4 bb0 = *(const float4*)&bo[m0 + d];
    float4 bb1 = *(const float4*)&bo[m0 + d + 4];
#pragma unroll
    for (int u = 0; u < 8; u++) {
        int n = n0 + ri*8 + u;
        float* dst = &out[(size_t)n*DD + m0 + d];
        *(float4*)&dst[0] = make_float4(acc[u][0]+bb0.x, acc[u][1]+bb0.y,
                                        acc[u][2]+bb0.z, acc[u][3]+bb0.w);
        *(float4*)&dst[4] = make_float4(acc[u][4]+bb1.x, acc[u][5]+bb1.y,
                                        acc[u][6]+bb1.z, acc[u][7]+bb1.w);
    }
}

// ---------------------------------------------------------------------------

static const int SC_SMEM = (QT*SS + 64*QTP + 64*JTP) * (int)sizeof(float); // 104448
static const int PV_SMEM = (JT*PVP + JT*64) * (int)sizeof(float);          // 100352

extern "C" void kernel_launch(void* const* d_in, const int* in_sizes, int n_in,
                              void* d_out, int out_size) {
    const float* x  = (const float*)d_in[0];
    const float* wq = (const float*)d_in[1];
    const float* bq = (const float*)d_in[2];
    const float* wk = (const float*)d_in[3];
    const float* bk = (const float*)d_in[4];
    const float* wv = (const float*)d_in[5];
    const float* bv = (const float*)d_in[6];
    const float* wo = (const float*)d_in[7];
    const float* bo = (const float*)d_in[8];
    const float* rb = (const float*)d_in[9];

    float* out      = (float*)d_out;
    float* out_attn = out + (size_t)BB*SS*DD;

    cudaFuncSetAttribute(scores_kernel, cudaFuncAttributeMaxDynamicSharedMemorySize, SC_SMEM);
    cudaFuncSetAttribute(pv_kernel, cudaFuncAttributeMaxDynamicSharedMemorySize, PV_SMEM);

    proj_qkv<<<dim3(DD/64, (BB*SS)/128, 3), 128>>>(x, wq, bq, wk, bk, wv, bv);

    scores_kernel<<<dim3(SS/QT, HH, BB), 256, SC_SMEM>>>(rb);

    mean_kernel<<<(BB*SS*(SS/4))/256, 256>>>(out_attn);

    pv_kernel<<<dim3((SS + PVQ - 1)/PVQ, HH, BB), 256, PV_SMEM>>>();

    out_proj<<<dim3(DD/64, (BB*SS)/128), 128>>>(wo, bo, out);
}

// round 13
// speedup vs baseline: 1.0913x; 1.0861x over previous
#include <cuda_runtime.h>
#include <math_constants.h>
#include <cstdint>

#define BB 32
#define SS 480
#define DD 512
#define HH 8
#define DK 64
#define ML 500
#define QT 32
#define JT 128
#define QTP 36
#define JTP 132
#define PVQ 128
#define PVP 132

__device__ float g_q[BB*HH*SS*DK];
__device__ float g_k[BB*HH*SS*DK];
__device__ float g_v[BB*HH*SS*DK];
__device__ float g_ctx[(size_t)BB*SS*DD];
__device__ float g_p[(size_t)BB*HH*SS*SS];   // raw scores, then probs in-place

// ---------------------------------------------------------------------------
// Kernel 1: fused QKV projection (R10/R12 version — known good).
// ---------------------------------------------------------------------------
__global__ __launch_bounds__(128) void proj_qkv(
    const float* __restrict__ x,
    const float* __restrict__ wq, const float* __restrict__ bq,
    const float* __restrict__ wk, const float* __restrict__ bk,
    const float* __restrict__ wv, const float* __restrict__ bv)
{
    const int z = blockIdx.z;
    const float* W    = (z == 0) ? wq : (z == 1) ? wk : wv;
    const float* bias = (z == 0) ? bq : (z == 1) ? bk : bv;
    float* Out        = (z == 0) ? g_q : (z == 1) ? g_k : g_v;

    __shared__ float Xs[32][132];
    __shared__ float Ws[32][68];

    const int m0 = blockIdx.x * 64;
    const int n0 = blockIdx.y * 128;
    const int tid = threadIdx.x;

    const int c8 = tid & 7,  xrow = tid >> 3;
    const int wc4 = tid & 15, wk_ = tid >> 4;
    const int ri = tid >> 3, ci = tid & 7;

    float acc[8][8] = {};
    float4 xr[8], wr[4];

#pragma unroll
    for (int rr = 0; rr < 8; rr++)
        xr[rr] = *(const float4*)&x[(size_t)(n0 + xrow + rr*16)*DD + c8*4];
#pragma unroll
    for (int tt = 0; tt < 4; tt++)
        wr[tt] = *(const float4*)&W[(size_t)(wk_ + tt*8)*DD + m0 + wc4*4];

    for (int k0 = 0; k0 < DD; k0 += 32) {
#pragma unroll
        for (int rr = 0; rr < 8; rr++) {
            int r = xrow + rr*16;
            Xs[c8*4+0][r] = xr[rr].x; Xs[c8*4+1][r] = xr[rr].y;
            Xs[c8*4+2][r] = xr[rr].z; Xs[c8*4+3][r] = xr[rr].w;
        }
#pragma unroll
        for (int tt = 0; tt < 4; tt++)
            *(float4*)&Ws[wk_ + tt*8][wc4*4] = wr[tt];
        __syncthreads();

        if (k0 + 32 < DD) {
#pragma unroll
            for (int rr = 0; rr < 8; rr++)
                xr[rr] = *(const float4*)&x[(size_t)(n0 + xrow + rr*16)*DD + k0 + 32 + c8*4];
#pragma unroll
            for (int tt = 0; tt < 4; tt++)
                wr[tt] = *(const float4*)&W[(size_t)(k0 + 32 + wk_ + tt*8)*DD + m0 + wc4*4];
        }

#pragma unroll
        for (int t = 0; t < 32; t++) {
            float4 a0 = *(const float4*)&Xs[t][ri*8];
            float4 a1 = *(const float4*)&Xs[t][ri*8+4];
            float4 b0 = *(const float4*)&Ws[t][ci*8];
            float4 b1 = *(const float4*)&Ws[t][ci*8+4];
            float av[8] = {a0.x,a0.y,a0.z,a0.w,a1.x,a1.y,a1.z,a1.w};
            float bw[8] = {b0.x,b0.y,b0.z,b0.w,b1.x,b1.y,b1.z,b1.w};
#pragma unroll
            for (int i = 0; i < 8; i++)
#pragma unroll
                for (int j = 0; j < 8; j++)
                    acc[i][j] += av[i] * bw[j];
        }
        __syncthreads();
    }

    const int h = m0 >> 6;
    const int d = ci*8;
    float4 bb0 = *(const float4*)&bias[m0 + d];
    float4 bb1 = *(const float4*)&bias[m0 + d + 4];
#pragma unroll
    for (int u = 0; u < 8; u++) {
        int n = n0 + ri*8 + u;
        int b = n / SS, s = n % SS;
        float* dst = &Out[(((size_t)b*HH + h)*SS + s)*DK + d];
        *(float4*)&dst[0] = make_float4(acc[u][0]+bb0.x, acc[u][1]+bb0.y,
                                        acc[u][2]+bb0.z, acc[u][3]+bb0.w);
        *(float4*)&dst[4] = make_float4(acc[u][4]+bb1.x, acc[u][5]+bb1.y,
                                        acc[u][6]+bb1.z, acc[u][7]+bb1.w);
    }
}

// ---------------------------------------------------------------------------
// Kernel 2a: scores GEMM.  S = q k^T / 8 + bias, causal-masked, raw -> g_p.
// 128 thr, C tile 32(i) x 128(j), thread tile 4i x (4+4)j, 43KB static smem.
// ---------------------------------------------------------------------------
__global__ __launch_bounds__(128) void scores_gemm(
    const float* __restrict__ rel_bias)
{
    __shared__ float qsT[64*QTP];    // [t][i]
    __shared__ float kvb[64*JTP];    // [t][j]

    const int i0 = blockIdx.x * QT;
    const int h  = blockIdx.y;
    const int b  = blockIdx.z;
    const int tid = threadIdx.x;

    const int jcount = i0 + QT;
    const int ntile  = (jcount + JT - 1) / JT;

    const float* qg = g_q + (((size_t)b*HH + h)*SS + i0)*DK;
    const float* kg = g_k + (((size_t)b*HH + h)*SS)*DK;
    float* sg = g_p + (((size_t)b*HH + h)*SS + i0)*SS;

    // q tile transposed: 2048 elems / 128 thr
#pragma unroll
    for (int it = 0; it < 16; it++) {
        int idx = tid + it*128;
        int i = idx >> 6, t = idx & 63;
        qsT[t*QTP + i] = qg[idx];
    }

    const int ig = tid >> 4;      // 8 groups of 4 rows
    const int jg = tid & 15;      // 16 groups; j cols jg*4 and 64+jg*4

    for (int jt = 0; jt < ntile; jt++) {
        const int j0 = jt * JT;
        __syncthreads();
#pragma unroll
        for (int it = 0; it < 64; it++) {
            int idx = tid + it*128;
            int jl = idx >> 6, t = idx & 63;
            int j = j0 + jl;
            kvb[t*JTP + jl] = (j < SS) ? kg[(size_t)j*DK + t] : 0.f;
        }
        __syncthreads();

        float acc[4][8] = {};
#pragma unroll
        for (int t = 0; t < 64; t++) {
            float4 a4 = *(const float4*)&qsT[t*QTP + ig*4];
            float4 b0 = *(const float4*)&kvb[t*JTP + jg*4];
            float4 b1 = *(const float4*)&kvb[t*JTP + 64 + jg*4];
            float av[4] = {a4.x, a4.y, a4.z, a4.w};
            float bw[8] = {b0.x,b0.y,b0.z,b0.w,b1.x,b1.y,b1.z,b1.w};
#pragma unroll
            for (int i = 0; i < 4; i++)
#pragma unroll
                for (int c = 0; c < 8; c++)
                    acc[i][c] += av[i] * bw[c];
        }

#pragma unroll
        for (int ii = 0; ii < 4; ii++) {
            const int i = i0 + ig*4 + ii;
            const float* brow = rel_bias + ((size_t)h*ML + i)*ML;
            float* srow = sg + (size_t)(ig*4 + ii)*SS;
#pragma unroll
            for (int half = 0; half < 2; half++) {
                const int jb = j0 + half*64 + jg*4;
                float vals[4];
#pragma unroll
                for (int jj = 0; jj < 4; jj++) {
                    int j = jb + jj;
                    vals[jj] = (j <= i && j < SS) ? acc[ii][half*4+jj]*0.125f + brow[j]
                                                  : -CUDART_INF_F;
                }
                if (jb + 3 < SS)
                    *(float4*)&srow[jb] = make_float4(vals[0], vals[1], vals[2], vals[3]);
                else {
#pragma unroll
                    for (int jj = 0; jj < 4; jj++)
                        if (jb + jj < SS) srow[jb + jj] = vals[jj];
                }
            }
        }
    }
}

// ---------------------------------------------------------------------------
// Kernel 2b: row softmax, in place.  One warp per row; whole row in regs.
// Writes exact zeros above the diagonal.
// ---------------------------------------------------------------------------
__global__ __launch_bounds__(256) void softmax_row()
{
    const int gid  = blockIdx.x * 8 + (threadIdx.x >> 5);  // row id over B*H*SS
    const int lane = threadIdx.x & 31;
    const int i = gid % SS;                                 // seq position
    const int n = i + 1;                                    // valid cols

    float* row = g_p + (size_t)gid * SS;

    float v[15];
    float m = -CUDART_INF_F;
#pragma unroll
    for (int k = 0; k < 15; k++) {
        int j = lane + k*32;
        v[k] = (j < n) ? row[j] : -CUDART_INF_F;
        m = fmaxf(m, v[k]);
    }
#pragma unroll
    for (int o = 16; o; o >>= 1) m = fmaxf(m, __shfl_xor_sync(0xffffffffu, m, o));

    float s = 0.f;
#pragma unroll
    for (int k = 0; k < 15; k++) {
        int j = lane + k*32;
        v[k] = (j < n) ? __expf(v[k] - m) : 0.f;
        s += v[k];
    }
#pragma unroll
    for (int o = 16; o; o >>= 1) s += __shfl_xor_sync(0xffffffffu, s, o);
    float inv = 1.f / s;

#pragma unroll
    for (int k = 0; k < 15; k++) {
        int j = lane + k*32;
        row[j] = v[k] * inv;
    }
}

// ---------------------------------------------------------------------------
// Kernel 3: attn mean over heads (unchanged).
// ---------------------------------------------------------------------------
__global__ __launch_bounds__(256) void mean_kernel(float* __restrict__ out_attn)
{
    const int gid = blockIdx.x * 256 + threadIdx.x;
    const int j4  = gid % (SS/4);
    int rest = gid / (SS/4);
    const int i = rest % SS;
    const int b = rest / SS;

    const int i0 = (i >> 5) << 5;
    const int jcap = min(SS, (((i0 + QT) + JT - 1) / JT) * JT);

    float4 s = make_float4(0.f, 0.f, 0.f, 0.f);
    if (j4*4 < jcap) {
        const float* base = g_p + (((size_t)b*HH)*SS + i)*SS + j4*4;
#pragma unroll
        for (int h = 0; h < HH; h++) {
            float4 v = *(const float4*)(base + (size_t)h*SS*SS);
            s.x += v.x; s.y += v.y; s.z += v.z; s.w += v.w;
        }
        s.x *= 0.125f; s.y *= 0.125f; s.z *= 0.125f; s.w *= 0.125f;
    }
    *(float4*)&out_attn[((size_t)b*SS + i)*SS + j4*4] = s;
}

// ---------------------------------------------------------------------------
// Kernel 4: ctx = P @ V.  (R12 version — best measured, 170us)
// ---------------------------------------------------------------------------
__global__ __launch_bounds__(256, 2) void pv_kernel()
{
    extern __shared__ float pvsm[];
    float* psT = pvsm;
    float* vs  = psT + JT*PVP;

    const int i0 = blockIdx.x * PVQ;
    const int h  = blockIdx.y;
    const int b  = blockIdx.z;
    const int tid = threadIdx.x;

    const int jcount = min(i0 + PVQ, SS);
    const int ntile  = (jcount + JT - 1) / JT;

    const float* vg = g_v + (((size_t)b*HH + h)*SS)*DK;
    const float* pg = g_p + (((size_t)b*HH + h)*SS + i0)*SS;

    const int rg = tid >> 4;
    const int cg = tid & 15;

    float acc[8][4] = {};

    for (int jt = 0; jt < ntile; jt++) {
        const int j0 = jt * JT;
        __syncthreads();
#pragma unroll
        for (int it = 0; it < 8; it++) {
            int idx = tid + it*256;
            int j = idx >> 4, d4 = idx & 15;
            float4 v = (j0 + j < SS)
                ? *(const float4*)&vg[(size_t)(j0 + j)*DK + d4*4]
                : make_float4(0.f,0.f,0.f,0.f);
            *(float4*)&vs[j*64 + d4*4] = v;
        }
#pragma unroll
        for (int it = 0; it < 64; it++) {
            int idx = tid + it*256;
            int r = idx >> 7, j = idx & 127;
            float p = (i0 + r < SS && j0 + j < SS) ? pg[(size_t)r*SS + j0 + j] : 0.f;
            psT[j*PVP + r] = p;
        }
        __syncthreads();

#pragma unroll 4
        for (int j = 0; j < JT; j++) {
            float4 a0 = *(const float4*)&psT[j*PVP + rg*8];
            float4 a1 = *(const float4*)&psT[j*PVP + rg*8 + 4];
            float4 b4 = *(const float4*)&vs[j*64 + cg*4];
            float av[8] = {a0.x,a0.y,a0.z,a0.w,a1.x,a1.y,a1.z,a1.w};
            float bw[4] = {b4.x,b4.y,b4.z,b4.w};
#pragma unroll
            for (int i = 0; i < 8; i++)
#pragma unroll
                for (int c = 0; c < 4; c++)
                    acc[i][c] += av[i] * bw[c];
        }
    }

#pragma unroll
    for (int i = 0; i < 8; i++) {
        int row = i0 + rg*8 + i;
        if (row < SS) {
            float* dst = g_ctx + ((size_t)b*SS + row)*DD + h*DK + cg*4;
            *(float4*)dst = make_float4(acc[i][0], acc[i][1], acc[i][2], acc[i][3]);
        }
    }
}

// ---------------------------------------------------------------------------
// Kernel 5: output projection (R10/R12 version).
// ---------------------------------------------------------------------------
__global__ __launch_bounds__(128) void out_proj(
    const float* __restrict__ wo, const float* __restrict__ bo,
    float* __restrict__ out)
{
    __shared__ float Xs[32][132];
    __shared__ float Ws[32][68];

    const int m0 = blockIdx.x * 64;
    const int n0 = blockIdx.y * 128;
    const int tid = threadIdx.x;

    const int c8 = tid & 7,  xrow = tid >> 3;
    const int wc4 = tid & 15, wk_ = tid >> 4;
    const int ri = tid >> 3, ci = tid & 7;

    float acc[8][8] = {};
    float4 xr[8], wr[4];

#pragma unroll
    for (int rr = 0; rr < 8; rr++)
        xr[rr] = *(const float4*)&g_ctx[(size_t)(n0 + xrow + rr*16)*DD + c8*4];
#pragma unroll
    for (int tt = 0; tt < 4; tt++)
        wr[tt] = *(const float4*)&wo[(size_t)(wk_ + tt*8)*DD + m0 + wc4*4];

    for (int k0 = 0; k0 < DD; k0 += 32) {
#pragma unroll
        for (int rr = 0; rr < 8; rr++) {
            int r = xrow + rr*16;
            Xs[c8*4+0][r] = xr[rr].x; Xs[c8*4+1][r] = xr[rr].y;
            Xs[c8*4+2][r] = xr[rr].z; Xs[c8*4+3][r] = xr[rr].w;
        }
#pragma unroll
        for (int tt = 0; tt < 4; tt++)
            *(float4*)&Ws[wk_ + tt*8][wc4*4] = wr[tt];
        __syncthreads();

        if (k0 + 32 < DD) {
#pragma unroll
            for (int rr = 0; rr < 8; rr++)
                xr[rr] = *(const float4*)&g_ctx[(size_t)(n0 + xrow + rr*16)*DD + k0 + 32 + c8*4];
#pragma unroll
            for (int tt = 0; tt < 4; tt++)
                wr[tt] = *(const float4*)&wo[(size_t)(k0 + 32 + wk_ + tt*8)*DD + m0 + wc4*4];
        }

#pragma unroll
        for (int t = 0; t < 32; t++) {
            float4 a0 = *(const float4*)&Xs[t][ri*8];
            float4 a1 = *(const float4*)&Xs[t][ri*8+4];
            float4 b0 = *(const float4*)&Ws[t][ci*8];
            float4 b1 = *(const float4*)&Ws[t][ci*8+4];
            float av[8] = {a0.x,a0.y,a0.z,a0.w,a1.x,a1.y,a1.z,a1.w};
            float bw[8] = {b0.x,b0.y,b0.z,b0.w,b1.x,b1.y,b1.z,b1.w};
#pragma unroll
            for (int i = 0; i < 8; i++)
#pragma unroll
                for (int j = 0; j < 8; j++)
                    acc[i][j] += av[i] * bw[j];
        }
        __syncthreads();
    }

    const int d = ci*8;
    float4 bb0 = *(const float4*)&bo[m0 + d];
    float4 bb1 = *(const float4*)&bo[m0 + d + 4];
#pragma unroll
    for (int u = 0; u < 8; u++) {
        int n = n0 + ri*8 + u;
        float* dst = &out[(size_t)n*DD + m0 + d];
        *(float4*)&dst[0] = make_float4(acc[u][0]+bb0.x, acc[u][1]+bb0.y,
                                        acc[u][2]+bb0.z, acc[u][3]+bb0.w);
        *(float4*)&dst[4] = make_float4(acc[u][4]+bb1.x, acc[u][5]+bb1.y,
                                        acc[u][6]+bb1.z, acc[u][7]+bb1.w);
    }
}

// ---------------------------------------------------------------------------

static const int PV_SMEM = (JT*PVP + JT*64) * (int)sizeof(float);   // 100352

extern "C" void kernel_launch(void* const* d_in, const int* in_sizes, int n_in,
                              void* d_out, int out_size) {
    const float* x  = (const float*)d_in[0];
    const float* wq = (const float*)d_in[1];
    const float* bq = (const float*)d_in[2];
    const float* wk = (const float*)d_in[3];
    const float* bk = (const float*)d_in[4];
    const float* wv = (const float*)d_in[5];
    const float* bv = (const float*)d_in[6];
    const float* wo = (const float*)d_in[7];
    const float* bo = (const float*)d_in[8];
    const float* rb = (const float*)d_in[9];

    float* out      = (float*)d_out;
    float* out_attn = out + (size_t)BB*SS*DD;

    cudaFuncSetAttribute(pv_kernel, cudaFuncAttributeMaxDynamicSharedMemorySize, PV_SMEM);

    proj_qkv<<<dim3(DD/64, (BB*SS)/128, 3), 128>>>(x, wq, bq, wk, bk, wv, bv);

    scores_gemm<<<dim3(SS/QT, HH, BB), 128>>>(rb);
    softmax_row<<<(BB*HH*SS)/8, 256>>>();

    mean_kernel<<<(BB*SS*(SS/4))/256, 256>>>(out_attn);

    pv_kernel<<<dim3((SS + PVQ - 1)/PVQ, HH, BB), 256, PV_SMEM>>>();

    out_proj<<<dim3(DD/64, (BB*SS)/128), 128>>>(wo, bo, out);
}

// round 14
// speedup vs baseline: 1.1754x; 1.0771x over previous
#include <cuda_runtime.h>
#include <math_constants.h>
#include <cstdint>

#define BB 32
#define SS 480
#define DD 512
#define HH 8
#define DK 64
#define ML 500
#define QT 32
#define JT 128
#define QB 64       // scores row band
#define QBP 68      // qsT row stride
#define JTP 132
#define PVQ 128
#define PVP 132

__device__ float g_q[BB*HH*SS*DK];
__device__ float g_k[BB*HH*SS*DK];
__device__ float g_v[BB*HH*SS*DK];
__device__ float g_ctx[(size_t)BB*SS*DD];
__device__ float g_p[(size_t)BB*HH*SS*SS];   // raw scores, then probs in-place

// ---------------------------------------------------------------------------
// Kernel 1: fused QKV projection (R10/R13 version — known good).
// ---------------------------------------------------------------------------
__global__ __launch_bounds__(128) void proj_qkv(
    const float* __restrict__ x,
    const float* __restrict__ wq, const float* __restrict__ bq,
    const float* __restrict__ wk, const float* __restrict__ bk,
    const float* __restrict__ wv, const float* __restrict__ bv)
{
    const int z = blockIdx.z;
    const float* W    = (z == 0) ? wq : (z == 1) ? wk : wv;
    const float* bias = (z == 0) ? bq : (z == 1) ? bk : bv;
    float* Out        = (z == 0) ? g_q : (z == 1) ? g_k : g_v;

    __shared__ float Xs[32][132];
    __shared__ float Ws[32][68];

    const int m0 = blockIdx.x * 64;
    const int n0 = blockIdx.y * 128;
    const int tid = threadIdx.x;

    const int c8 = tid & 7,  xrow = tid >> 3;
    const int wc4 = tid & 15, wk_ = tid >> 4;
    const int ri = tid >> 3, ci = tid & 7;

    float acc[8][8] = {};
    float4 xr[8], wr[4];

#pragma unroll
    for (int rr = 0; rr < 8; rr++)
        xr[rr] = *(const float4*)&x[(size_t)(n0 + xrow + rr*16)*DD + c8*4];
#pragma unroll
    for (int tt = 0; tt < 4; tt++)
        wr[tt] = *(const float4*)&W[(size_t)(wk_ + tt*8)*DD + m0 + wc4*4];

    for (int k0 = 0; k0 < DD; k0 += 32) {
#pragma unroll
        for (int rr = 0; rr < 8; rr++) {
            int r = xrow + rr*16;
            Xs[c8*4+0][r] = xr[rr].x; Xs[c8*4+1][r] = xr[rr].y;
            Xs[c8*4+2][r] = xr[rr].z; Xs[c8*4+3][r] = xr[rr].w;
        }
#pragma unroll
        for (int tt = 0; tt < 4; tt++)
            *(float4*)&Ws[wk_ + tt*8][wc4*4] = wr[tt];
        __syncthreads();

        if (k0 + 32 < DD) {
#pragma unroll
            for (int rr = 0; rr < 8; rr++)
                xr[rr] = *(const float4*)&x[(size_t)(n0 + xrow + rr*16)*DD + k0 + 32 + c8*4];
#pragma unroll
            for (int tt = 0; tt < 4; tt++)
                wr[tt] = *(const float4*)&W[(size_t)(k0 + 32 + wk_ + tt*8)*DD + m0 + wc4*4];
        }

#pragma unroll
        for (int t = 0; t < 32; t++) {
            float4 a0 = *(const float4*)&Xs[t][ri*8];
            float4 a1 = *(const float4*)&Xs[t][ri*8+4];
            float4 b0 = *(const float4*)&Ws[t][ci*8];
            float4 b1 = *(const float4*)&Ws[t][ci*8+4];
            float av[8] = {a0.x,a0.y,a0.z,a0.w,a1.x,a1.y,a1.z,a1.w};
            float bw[8] = {b0.x,b0.y,b0.z,b0.w,b1.x,b1.y,b1.z,b1.w};
#pragma unroll
            for (int i = 0; i < 8; i++)
#pragma unroll
                for (int j = 0; j < 8; j++)
                    acc[i][j] += av[i] * bw[j];
        }
        __syncthreads();
    }

    const int h = m0 >> 6;
    const int d = ci*8;
    float4 bb0 = *(const float4*)&bias[m0 + d];
    float4 bb1 = *(const float4*)&bias[m0 + d + 4];
#pragma unroll
    for (int u = 0; u < 8; u++) {
        int n = n0 + ri*8 + u;
        int b = n / SS, s = n % SS;
        float* dst = &Out[(((size_t)b*HH + h)*SS + s)*DK + d];
        *(float4*)&dst[0] = make_float4(acc[u][0]+bb0.x, acc[u][1]+bb0.y,
                                        acc[u][2]+bb0.z, acc[u][3]+bb0.w);
        *(float4*)&dst[4] = make_float4(acc[u][4]+bb1.x, acc[u][5]+bb1.y,
                                        acc[u][6]+bb1.z, acc[u][7]+bb1.w);
    }
}

// ---------------------------------------------------------------------------
// Kernel 2a: scores GEMM.  64-row bands, 256 thr, C tile 64x128,
// thread tile 4i x (4+4)j.  K-tile fills per (b,h): 20 (was 36).
// ---------------------------------------------------------------------------
__global__ __launch_bounds__(256) void scores_gemm(
    const float* __restrict__ rel_bias)
{
    __shared__ float qsT[64*QBP];    // [t][i], i < 64
    __shared__ float kvb[64*JTP];    // [t][j]

    const int i0 = blockIdx.x * QB;
    const int h  = blockIdx.y;
    const int b  = blockIdx.z;
    const int tid = threadIdx.x;

    const int rows   = min(QB, SS - i0);
    const int jcount = min(i0 + QB, SS);
    const int ntile  = (jcount + JT - 1) / JT;

    const float* qg = g_q + (((size_t)b*HH + h)*SS + i0)*DK;
    const float* kg = g_k + (((size_t)b*HH + h)*SS)*DK;
    float* sg = g_p + (((size_t)b*HH + h)*SS + i0)*SS;

    // q band transposed: 64x64 = 4096 elems / 256 thr = 16 iters
#pragma unroll
    for (int it = 0; it < 16; it++) {
        int idx = tid + it*256;
        int i = idx >> 6, t = idx & 63;
        qsT[t*QBP + i] = (i < rows) ? qg[(size_t)i*DK + t] : 0.f;
    }

    const int ig = tid >> 4;      // 16 groups of 4 rows
    const int jg = tid & 15;      // j cols jg*4 and 64+jg*4

    for (int jt = 0; jt < ntile; jt++) {
        const int j0 = jt * JT;
        __syncthreads();
#pragma unroll
        for (int it = 0; it < 32; it++) {
            int idx = tid + it*256;
            int jl = idx >> 6, t = idx & 63;
            int j = j0 + jl;
            kvb[t*JTP + jl] = (j < SS) ? kg[(size_t)j*DK + t] : 0.f;
        }
        __syncthreads();

        float acc[4][8] = {};
#pragma unroll
        for (int t = 0; t < 64; t++) {
            float4 a4 = *(const float4*)&qsT[t*QBP + ig*4];
            float4 b0 = *(const float4*)&kvb[t*JTP + jg*4];
            float4 b1 = *(const float4*)&kvb[t*JTP + 64 + jg*4];
            float av[4] = {a4.x, a4.y, a4.z, a4.w};
            float bw[8] = {b0.x,b0.y,b0.z,b0.w,b1.x,b1.y,b1.z,b1.w};
#pragma unroll
            for (int i = 0; i < 4; i++)
#pragma unroll
                for (int c = 0; c < 8; c++)
                    acc[i][c] += av[i] * bw[c];
        }

#pragma unroll
        for (int ii = 0; ii < 4; ii++) {
            const int il = ig*4 + ii;
            if (il >= rows) break;
            const int i = i0 + il;
            const float* brow = rel_bias + ((size_t)h*ML + i)*ML;
            float* srow = sg + (size_t)il*SS;
#pragma unroll
            for (int half = 0; half < 2; half++) {
                const int jb = j0 + half*64 + jg*4;
                float vals[4];
#pragma unroll
                for (int jj = 0; jj < 4; jj++) {
                    int j = jb + jj;
                    vals[jj] = (j <= i && j < SS) ? acc[ii][half*4+jj]*0.125f + brow[j]
                                                  : -CUDART_INF_F;
                }
                if (jb + 3 < SS)
                    *(float4*)&srow[jb] = make_float4(vals[0], vals[1], vals[2], vals[3]);
                else {
#pragma unroll
                    for (int jj = 0; jj < 4; jj++)
                        if (jb + jj < SS) srow[jb + jj] = vals[jj];
                }
            }
        }
    }
}

// ---------------------------------------------------------------------------
// Kernel 2b: row softmax, in place.  One warp per row; row in registers.
// ---------------------------------------------------------------------------
__global__ __launch_bounds__(256) void softmax_row()
{
    const int gid  = blockIdx.x * 8 + (threadIdx.x >> 5);
    const int lane = threadIdx.x & 31;
    const int i = gid % SS;
    const int n = i + 1;

    float* row = g_p + (size_t)gid * SS;

    float v[15];
    float m = -CUDART_INF_F;
#pragma unroll
    for (int k = 0; k < 15; k++) {
        int j = lane + k*32;
        v[k] = (j < n) ? row[j] : -CUDART_INF_F;
        m = fmaxf(m, v[k]);
    }
#pragma unroll
    for (int o = 16; o; o >>= 1) m = fmaxf(m, __shfl_xor_sync(0xffffffffu, m, o));

    float s = 0.f;
#pragma unroll
    for (int k = 0; k < 15; k++) {
        int j = lane + k*32;
        v[k] = (j < n) ? __expf(v[k] - m) : 0.f;
        s += v[k];
    }
#pragma unroll
    for (int o = 16; o; o >>= 1) s += __shfl_xor_sync(0xffffffffu, s, o);
    float inv = 1.f / s;

#pragma unroll
    for (int k = 0; k < 15; k++) {
        int j = lane + k*32;
        row[j] = v[k] * inv;
    }
}

// ---------------------------------------------------------------------------
// Kernel 3: attn mean over heads (unchanged — 75% DRAM).
// ---------------------------------------------------------------------------
__global__ __launch_bounds__(256) void mean_kernel(float* __restrict__ out_attn)
{
    const int gid = blockIdx.x * 256 + threadIdx.x;
    const int j4  = gid % (SS/4);
    int rest = gid / (SS/4);
    const int i = rest % SS;
    const int b = rest / SS;

    const int i0 = (i >> 5) << 5;
    const int jcap = min(SS, (((i0 + QT) + JT - 1) / JT) * JT);

    float4 s = make_float4(0.f, 0.f, 0.f, 0.f);
    if (j4*4 < jcap) {
        const float* base = g_p + (((size_t)b*HH)*SS + i)*SS + j4*4;
#pragma unroll
        for (int h = 0; h < HH; h++) {
            float4 v = *(const float4*)(base + (size_t)h*SS*SS);
            s.x += v.x; s.y += v.y; s.z += v.z; s.w += v.w;
        }
        s.x *= 0.125f; s.y *= 0.125f; s.z *= 0.125f; s.w *= 0.125f;
    }
    *(float4*)&out_attn[((size_t)b*SS + i)*SS + j4*4] = s;
}

// ---------------------------------------------------------------------------
// Kernel 4: ctx = P @ V.  (R12/R13 version — best measured)
// ---------------------------------------------------------------------------
__global__ __launch_bounds__(256, 2) void pv_kernel()
{
    extern __shared__ float pvsm[];
    float* psT = pvsm;
    float* vs  = psT + JT*PVP;

    const int i0 = blockIdx.x * PVQ;
    const int h  = blockIdx.y;
    const int b  = blockIdx.z;
    const int tid = threadIdx.x;

    const int jcount = min(i0 + PVQ, SS);
    const int ntile  = (jcount + JT - 1) / JT;

    const float* vg = g_v + (((size_t)b*HH + h)*SS)*DK;
    const float* pg = g_p + (((size_t)b*HH + h)*SS + i0)*SS;

    const int rg = tid >> 4;
    const int cg = tid & 15;

    float acc[8][4] = {};

    for (int jt = 0; jt < ntile; jt++) {
        const int j0 = jt * JT;
        __syncthreads();
#pragma unroll
        for (int it = 0; it < 8; it++) {
            int idx = tid + it*256;
            int j = idx >> 4, d4 = idx & 15;
            float4 v = (j0 + j < SS)
                ? *(const float4*)&vg[(size_t)(j0 + j)*DK + d4*4]
                : make_float4(0.f,0.f,0.f,0.f);
            *(float4*)&vs[j*64 + d4*4] = v;
        }
#pragma unroll
        for (int it = 0; it < 64; it++) {
            int idx = tid + it*256;
            int r = idx >> 7, j = idx & 127;
            float p = (i0 + r < SS && j0 + j < SS) ? pg[(size_t)r*SS + j0 + j] : 0.f;
            psT[j*PVP + r] = p;
        }
        __syncthreads();

#pragma unroll 4
        for (int j = 0; j < JT; j++) {
            float4 a0 = *(const float4*)&psT[j*PVP + rg*8];
            float4 a1 = *(const float4*)&psT[j*PVP + rg*8 + 4];
            float4 b4 = *(const float4*)&vs[j*64 + cg*4];
            float av[8] = {a0.x,a0.y,a0.z,a0.w,a1.x,a1.y,a1.z,a1.w};
            float bw[4] = {b4.x,b4.y,b4.z,b4.w};
#pragma unroll
            for (int i = 0; i < 8; i++)
#pragma unroll
                for (int c = 0; c < 4; c++)
                    acc[i][c] += av[i] * bw[c];
        }
    }

#pragma unroll
    for (int i = 0; i < 8; i++) {
        int row = i0 + rg*8 + i;
        if (row < SS) {
            float* dst = g_ctx + ((size_t)b*SS + row)*DD + h*DK + cg*4;
            *(float4*)dst = make_float4(acc[i][0], acc[i][1], acc[i][2], acc[i][3]);
        }
    }
}

// ---------------------------------------------------------------------------
// Kernel 5: output projection (R10/R13 version).
// ---------------------------------------------------------------------------
__global__ __launch_bounds__(128) void out_proj(
    const float* __restrict__ wo, const float* __restrict__ bo,
    float* __restrict__ out)
{
    __shared__ float Xs[32][132];
    __shared__ float Ws[32][68];

    const int m0 = blockIdx.x * 64;
    const int n0 = blockIdx.y * 128;
    const int tid = threadIdx.x;

    const int c8 = tid & 7,  xrow = tid >> 3;
    const int wc4 = tid & 15, wk_ = tid >> 4;
    const int ri = tid >> 3, ci = tid & 7;

    float acc[8][8] = {};
    float4 xr[8], wr[4];

#pragma unroll
    for (int rr = 0; rr < 8; rr++)
        xr[rr] = *(const float4*)&g_ctx[(size_t)(n0 + xrow + rr*16)*DD + c8*4];
#pragma unroll
    for (int tt = 0; tt < 4; tt++)
        wr[tt] = *(const float4*)&wo[(size_t)(wk_ + tt*8)*DD + m0 + wc4*4];

    for (int k0 = 0; k0 < DD; k0 += 32) {
#pragma unroll
        for (int rr = 0; rr < 8; rr++) {
            int r = xrow + rr*16;
            Xs[c8*4+0][r] = xr[rr].x; Xs[c8*4+1][r] = xr[rr].y;
            Xs[c8*4+2][r] = xr[rr].z; Xs[c8*4+3][r] = xr[rr].w;
        }
#pragma unroll
        for (int tt = 0; tt < 4; tt++)
            *(float4*)&Ws[wk_ + tt*8][wc4*4] = wr[tt];
        __syncthreads();

        if (k0 + 32 < DD) {
#pragma unroll
            for (int rr = 0; rr < 8; rr++)
                xr[rr] = *(const float4*)&g_ctx[(size_t)(n0 + xrow + rr*16)*DD + k0 + 32 + c8*4];
#pragma unroll
            for (int tt = 0; tt < 4; tt++)
                wr[tt] = *(const float4*)&wo[(size_t)(k0 + 32 + wk_ + tt*8)*DD + m0 + wc4*4];
        }

#pragma unroll
        for (int t = 0; t < 32; t++) {
            float4 a0 = *(const float4*)&Xs[t][ri*8];
            float4 a1 = *(const float4*)&Xs[t][ri*8+4];
            float4 b0 = *(const float4*)&Ws[t][ci*8];
            float4 b1 = *(const float4*)&Ws[t][ci*8+4];
            float av[8] = {a0.x,a0.y,a0.z,a0.w,a1.x,a1.y,a1.z,a1.w};
            float bw[8] = {b0.x,b0.y,b0.z,b0.w,b1.x,b1.y,b1.z,b1.w};
#pragma unroll
            for (int i = 0; i < 8; i++)
#pragma unroll
                for (int j = 0; j < 8; j++)
                    acc[i][j] += av[i] * bw[j];
        }
        __syncthreads();
    }

    const int d = ci*8;
    float4 bb0 = *(const float4*)&bo[m0 + d];
    float4 bb1 = *(const float4*)&bo[m0 + d + 4];
#pragma unroll
    for (int u = 0; u < 8; u++) {
        int n = n0 + ri*8 + u;
        float* dst = &out[(size_t)n*DD + m0 + d];
        *(float4*)&dst[0] = make_float4(acc[u][0]+bb0.x, acc[u][1]+bb0.y,
                                        acc[u][2]+bb0.z, acc[u][3]+bb0.w);
        *(float4*)&dst[4] = make_float4(acc[u][4]+bb1.x, acc[u][5]+bb1.y,
                                        acc[u][6]+bb1.z, acc[u][7]+bb1.w);
    }
}

// ---------------------------------------------------------------------------

static const int PV_SMEM = (JT*PVP + JT*64) * (int)sizeof(float);   // 100352

extern "C" void kernel_launch(void* const* d_in, const int* in_sizes, int n_in,
                              void* d_out, int out_size) {
    const float* x  = (const float*)d_in[0];
    const float* wq = (const float*)d_in[1];
    const float* bq = (const float*)d_in[2];
    const float* wk = (const float*)d_in[3];
    const float* bk = (const float*)d_in[4];
    const float* wv = (const float*)d_in[5];
    const float* bv = (const float*)d_in[6];
    const float* wo = (const float*)d_in[7];
    const float* bo = (const float*)d_in[8];
    const float* rb = (const float*)d_in[9];

    float* out      = (float*)d_out;
    float* out_attn = out + (size_t)BB*SS*DD;

    cudaFuncSetAttribute(pv_kernel, cudaFuncAttributeMaxDynamicSharedMemorySize, PV_SMEM);

    proj_qkv<<<dim3(DD/64, (BB*SS)/128, 3), 128>>>(x, wq, bq, wk, bk, wv, bv);

    scores_gemm<<<dim3((SS + QB - 1)/QB, HH, BB), 256>>>(rb);
    softmax_row<<<(BB*HH*SS)/8, 256>>>();

    mean_kernel<<<(BB*SS*(SS/4))/256, 256>>>(out_attn);

    pv_kernel<<<dim3((SS + PVQ - 1)/PVQ, HH, BB), 256, PV_SMEM>>>();

    out_proj<<<dim3(DD/64, (BB*SS)/128), 128>>>(wo, bo, out);
}